// round 1
// baseline (speedup 1.0000x reference)
#include <cuda_runtime.h>

#define NN   100000
#define EE   640000
#define HD   128
#define NT   3
#define PD   64
#define NPOS 513
#define VEMB 96

// ---------------- device scratch (no allocations allowed) ----------------
static __device__ float d_h[NN * HD];          // 51.2 MB
static __device__ float d_h0[NN * HD];         // 51.2 MB
static __device__ float d_agg[NN * HD];        // 51.2 MB
static __device__ float d_u[NT * NN * HD];     // 153.6 MB
static __device__ float d_gate[NPOS * HD];     // 262 KB
static __device__ float d_cntT[NT * NN];
static __device__ float d_invden[NN];
static __device__ float d_WihT[HD * 3 * HD];   // [k][o]
static __device__ float d_WhhT[HD * 3 * HD];

// ---------------- prep kernels ----------------

// gate table: gate[p][j] = 2*sigmoid(pos_enc[p] @ Wg + bg)[j]
__global__ void gate_kernel(const float* __restrict__ pos_enc,
                            const float* __restrict__ Wg,
                            const float* __restrict__ bg) {
    int p = blockIdx.x, j = threadIdx.x;
    __shared__ float pe[PD];
    if (j < PD) pe[j] = pos_enc[p * PD + j];
    __syncthreads();
    float acc = bg[j];
#pragma unroll
    for (int k = 0; k < PD; k++) acc = fmaf(pe[k], Wg[k * HD + j], acc);
    d_gate[p * HD + j] = 2.0f / (1.0f + expf(-acc));
}

// transpose GRU weights: WihT[k][o] = W_ih[o][k]  (coalesced consumer reads)
__global__ void transpose_w(const float* __restrict__ Wih,
                            const float* __restrict__ Whh) {
    int idx = blockIdx.x * blockDim.x + threadIdx.x;
    if (idx < 3 * HD * HD) {
        int o = idx / HD, k = idx % HD;
        d_WihT[k * (3 * HD) + o] = Wih[idx];
        d_WhhT[k * (3 * HD) + o] = Whh[idx];
    }
}

// h0 = concat(emb[x], selectors); h = h0
__global__ void init_h(const int* __restrict__ xidx,
                       const float* __restrict__ sel,
                       const float* __restrict__ emb) {
    int v = blockIdx.x, j = threadIdx.x;
    float val = (j < VEMB) ? emb[xidx[v] * VEMB + j] : sel[v * 32 + (j - VEMB)];
    d_h0[v * HD + j] = val;
    d_h[v * HD + j]  = val;
}

__global__ void zero_cnt() {
    int i = blockIdx.x * blockDim.x + threadIdx.x;
    if (i < NT * NN) d_cntT[i] = 0.0f;
}

__global__ void cnt_kernel(const int* __restrict__ dst, const int* __restrict__ etype) {
    int e = blockIdx.x * blockDim.x + threadIdx.x;
    if (e < EE) atomicAdd(&d_cntT[etype[e] * NN + dst[e]], 1.0f);
}

__global__ void invden_kernel() {
    int v = blockIdx.x * blockDim.x + threadIdx.x;
    if (v < NN) {
        float t = d_cntT[v] + d_cntT[NN + v] + d_cntT[2 * NN + v];
        d_invden[v] = 1.0f / fmaxf(t, 1.0f);
    }
}

// ---------------- per-iteration kernels ----------------

__global__ void zero_u() {
    int i = blockIdx.x * blockDim.x + threadIdx.x;
    const int n4 = NT * NN * HD / 4;
    if (i < n4) ((float4*)d_u)[i] = make_float4(0.f, 0.f, 0.f, 0.f);
}

// one warp per edge: u[type][dst] += h[src] * gate[pos]
__global__ void scatter_kernel(const int* __restrict__ src, const int* __restrict__ dst,
                               const int* __restrict__ etype, const int* __restrict__ epos) {
    int e = (blockIdx.x * blockDim.x + threadIdx.x) >> 5;
    int lane = threadIdx.x & 31;
    if (e >= EE) return;
    int s = src[e], d = dst[e], t = etype[e], p = epos[e];
    float4 hv = *(const float4*)&d_h[s * HD + lane * 4];
    float4 gv = *(const float4*)&d_gate[p * HD + lane * 4];
    float* base = &d_u[(t * NN + d) * HD + lane * 4];
    atomicAdd(base + 0, hv.x * gv.x);
    atomicAdd(base + 1, hv.y * gv.y);
    atomicAdd(base + 2, hv.z * gv.z);
    atomicAdd(base + 3, hv.w * gv.w);
}

// agg[v] = (sum_t u[t][v] @ Wt[t] + sum_t cnt_t[v]*bt[t]) * invden[v]
// block: 64 rows x 128 cols, 256 threads, thread = 8 rows x 4 cols
__global__ void agg_gemm(const float* __restrict__ Wt, const float* __restrict__ bt) {
    __shared__ float As[64][HD];
    int r0 = blockIdx.x * 64;
    int tid = threadIdx.x;
    int cg = tid & 31;   // col group
    int rg = tid >> 5;   // row group 0..7
    int c0 = cg * 4;
    float acc[8][4] = {};
    for (int t = 0; t < NT; t++) {
        for (int i = tid; i < 64 * (HD / 4); i += 256) {
            int row = i >> 5, c4 = i & 31;
            int v = r0 + row;
            float4 val = (v < NN) ? ((const float4*)&d_u[(t * NN + v) * HD])[c4]
                                  : make_float4(0.f, 0.f, 0.f, 0.f);
            ((float4*)&As[row][0])[c4] = val;
        }
        __syncthreads();
        const float* Wtt = Wt + t * HD * HD;
#pragma unroll 4
        for (int k = 0; k < HD; k++) {
            float4 b = *(const float4*)&Wtt[k * HD + c0];
#pragma unroll
            for (int i = 0; i < 8; i++) {
                float a = As[rg * 8 + i][k];
                acc[i][0] = fmaf(a, b.x, acc[i][0]);
                acc[i][1] = fmaf(a, b.y, acc[i][1]);
                acc[i][2] = fmaf(a, b.z, acc[i][2]);
                acc[i][3] = fmaf(a, b.w, acc[i][3]);
            }
        }
        __syncthreads();
    }
    float4 bt0 = *(const float4*)&bt[0 * HD + c0];
    float4 bt1 = *(const float4*)&bt[1 * HD + c0];
    float4 bt2 = *(const float4*)&bt[2 * HD + c0];
#pragma unroll
    for (int i = 0; i < 8; i++) {
        int v = r0 + rg * 8 + i;
        if (v < NN) {
            float inv = d_invden[v];
            float n0 = d_cntT[v], n1 = d_cntT[NN + v], n2 = d_cntT[2 * NN + v];
            float4 o;
            o.x = (acc[i][0] + n0 * bt0.x + n1 * bt1.x + n2 * bt2.x) * inv;
            o.y = (acc[i][1] + n0 * bt0.y + n1 * bt1.y + n2 * bt2.y) * inv;
            o.z = (acc[i][2] + n0 * bt0.z + n1 * bt1.z + n2 * bt2.z) * inv;
            o.w = (acc[i][3] + n0 * bt0.w + n1 * bt1.w + n2 * bt2.w) * inv;
            *(float4*)&d_agg[v * HD + c0] = o;
        }
    }
}

// GRU cell, in-place on d_h. block: 16 nodes, 256 threads (128 cols x 2 node halves x 8 nodes)
__global__ void gru_kernel(const float* __restrict__ b_ih, const float* __restrict__ b_hh) {
    __shared__ float Ag[16][HD];
    __shared__ float Hs[16][HD];
    int n0 = blockIdx.x * 16;
    int tid = threadIdx.x;
    int j = tid & 127;
    int half = tid >> 7;
    for (int i = tid; i < 16 * (HD / 4); i += 256) {
        int row = i >> 5, c4 = i & 31;
        int v = n0 + row;
        float4 a = (v < NN) ? ((const float4*)&d_agg[v * HD])[c4] : make_float4(0.f, 0.f, 0.f, 0.f);
        float4 h = (v < NN) ? ((const float4*)&d_h[v * HD])[c4]   : make_float4(0.f, 0.f, 0.f, 0.f);
        ((float4*)&Ag[row][0])[c4] = a;
        ((float4*)&Hs[row][0])[c4] = h;
    }
    __syncthreads();
    float air[8] = {}, aiz[8] = {}, ain[8] = {}, ahr[8] = {}, ahz[8] = {}, ahn[8] = {};
#pragma unroll 2
    for (int k = 0; k < HD; k++) {
        float wir = d_WihT[k * 384 + j];
        float wiz = d_WihT[k * 384 + 128 + j];
        float win = d_WihT[k * 384 + 256 + j];
        float whr = d_WhhT[k * 384 + j];
        float whz = d_WhhT[k * 384 + 128 + j];
        float whn = d_WhhT[k * 384 + 256 + j];
#pragma unroll
        for (int n = 0; n < 8; n++) {
            float a  = Ag[half * 8 + n][k];
            float hv = Hs[half * 8 + n][k];
            air[n] = fmaf(a, wir, air[n]);
            aiz[n] = fmaf(a, wiz, aiz[n]);
            ain[n] = fmaf(a, win, ain[n]);
            ahr[n] = fmaf(hv, whr, ahr[n]);
            ahz[n] = fmaf(hv, whz, ahz[n]);
            ahn[n] = fmaf(hv, whn, ahn[n]);
        }
    }
    float bir = b_ih[j], biz = b_ih[128 + j], bin = b_ih[256 + j];
    float bhr = b_hh[j], bhz = b_hh[128 + j], bhn = b_hh[256 + j];
#pragma unroll
    for (int n = 0; n < 8; n++) {
        int v = n0 + half * 8 + n;
        if (v < NN) {
            float r  = 1.0f / (1.0f + expf(-(air[n] + ahr[n] + bir + bhr)));
            float z  = 1.0f / (1.0f + expf(-(aiz[n] + ahz[n] + biz + bhz)));
            float nn = tanhf(ain[n] + bin + r * (ahn[n] + bhn));
            float hp = Hs[half * 8 + n][j];
            d_h[v * HD + j] = (1.0f - z) * nn + z * hp;
        }
    }
}

// logits = relu([h,h0] @ W1 + b1) @ W2 + b2, one block per node
__global__ void readout_kernel(const float* __restrict__ W1, const float* __restrict__ b1,
                               const float* __restrict__ W2, const float* __restrict__ b2,
                               float* __restrict__ out) {
    int v = blockIdx.x, j = threadIdx.x;
    __shared__ float sh[HD], sh0[HD];
    __shared__ float wsum[4];
    sh[j]  = d_h[v * HD + j];
    sh0[j] = d_h0[v * HD + j];
    __syncthreads();
    float acc = b1[j];
#pragma unroll 4
    for (int k = 0; k < HD; k++) acc = fmaf(sh[k], W1[k * HD + j], acc);
#pragma unroll 4
    for (int k = 0; k < HD; k++) acc = fmaf(sh0[k], W1[(HD + k) * HD + j], acc);
    float f = fmaxf(acc, 0.0f) * W2[j];
#pragma unroll
    for (int off = 16; off; off >>= 1) f += __shfl_down_sync(0xffffffffu, f, off);
    if ((j & 31) == 0) wsum[j >> 5] = f;
    __syncthreads();
    if (j == 0) out[v] = wsum[0] + wsum[1] + wsum[2] + wsum[3] + b2[0];
}

// ---------------- launch ----------------
extern "C" void kernel_launch(void* const* d_in, const int* in_sizes, int n_in,
                              void* d_out, int out_size) {
    const int*   xidx    = (const int*)d_in[0];
    const float* sel     = (const float*)d_in[1];
    const int*   eidx    = (const int*)d_in[2];
    const int*   etype   = (const int*)d_in[3];
    const int*   epos    = (const int*)d_in[4];
    const float* emb     = (const float*)d_in[5];
    const float* pos_enc = (const float*)d_in[6];
    const float* Wg      = (const float*)d_in[7];
    const float* bg      = (const float*)d_in[8];
    const float* Wt      = (const float*)d_in[9];
    const float* bt      = (const float*)d_in[10];
    const float* Wih     = (const float*)d_in[11];
    const float* Whh     = (const float*)d_in[12];
    const float* bih     = (const float*)d_in[13];
    const float* bhh     = (const float*)d_in[14];
    const float* W1      = (const float*)d_in[15];
    const float* b1      = (const float*)d_in[16];
    const float* W2      = (const float*)d_in[17];
    const float* b2      = (const float*)d_in[18];
    const int* src = eidx;
    const int* dst = eidx + EE;
    float* out = (float*)d_out;

    gate_kernel<<<NPOS, HD>>>(pos_enc, Wg, bg);
    transpose_w<<<(3 * HD * HD + 255) / 256, 256>>>(Wih, Whh);
    init_h<<<NN, HD>>>(xidx, sel, emb);
    zero_cnt<<<(NT * NN + 255) / 256, 256>>>();
    cnt_kernel<<<(EE + 255) / 256, 256>>>(dst, etype);
    invden_kernel<<<(NN + 255) / 256, 256>>>();

    for (int it = 0; it < 6; it++) {
        zero_u<<<(NT * NN * HD / 4 + 255) / 256, 256>>>();
        scatter_kernel<<<(EE * 32 + 255) / 256, 256>>>(src, dst, etype, epos);
        agg_gemm<<<(NN + 63) / 64, 256>>>(Wt, bt);
        gru_kernel<<<(NN + 15) / 16, 256>>>(bih, bhh);
    }
    readout_kernel<<<NN, HD>>>(W1, b1, W2, b2, out);
}

// round 4
// speedup vs baseline: 1.8872x; 1.8872x over previous
#include <cuda_runtime.h>
#include <cstdint>

#define NN   100000
#define EE   640000
#define HD   128
#define NT   3
#define PD   64
#define NPOS 513
#define VEMB 96
#define NT64 1563          // ceil(100000/64)
#define AP   132           // smem pitch (floats)

// ---------------- device scratch ----------------
static __device__ float d_h[NN * HD];
static __device__ float d_h0[NN * HD];
static __device__ float d_u[NT * NN * HD];
static __device__ float d_gate[NPOS * HD];
static __device__ float d_cntT[NT * NN];
static __device__ float d_invden[NN];
static __device__ float d_Bw[11 * 16384];   // tf32-rounded weight chunks, row-major [k][n]

// ---------------- helpers ----------------
__device__ __forceinline__ unsigned to_tf32(float f) {
    unsigned r; asm("cvt.rna.tf32.f32 %0, %1;" : "=r"(r) : "f"(f)); return r;
}
__device__ __forceinline__ float sigf(float x) { return 1.0f / (1.0f + expf(-x)); }

// warp-level tf32 MMA: D(16x8) += A(16x8,row) * B(8x8,col)
// acc[nt][0]=C[g][2t] [1]=C[g][2t+1] [2]=C[g+8][2t] [3]=C[g+8][2t+1]
template<bool CVTA>
__device__ __forceinline__ void gemm_tile(const float* __restrict__ Amat,
                                          const float* __restrict__ Bmat,
                                          int r0, int c0, int g, int tig,
                                          float acc[8][4]) {
#pragma unroll 4
    for (int ks = 0; ks < 16; ks++) {
        int k0 = ks * 8;
        const float* ap = Amat + (r0 + g) * AP + k0 + tig;
        float f0 = ap[0], f1 = ap[8 * AP], f2 = ap[4], f3 = ap[8 * AP + 4];
        unsigned a0, a1, a2, a3;
        if (CVTA) {
            a0 = to_tf32(f0); a1 = to_tf32(f1); a2 = to_tf32(f2); a3 = to_tf32(f3);
        } else {
            a0 = __float_as_uint(f0); a1 = __float_as_uint(f1);
            a2 = __float_as_uint(f2); a3 = __float_as_uint(f3);
        }
        const float* bp = Bmat + (k0 + tig) * AP + c0 + g;
#pragma unroll
        for (int nt = 0; nt < 8; nt++) {
            unsigned b0 = __float_as_uint(bp[nt * 8]);
            unsigned b1 = __float_as_uint(bp[4 * AP + nt * 8]);
            asm volatile("mma.sync.aligned.m16n8k8.row.col.f32.tf32.tf32.f32 "
                         "{%0,%1,%2,%3}, {%4,%5,%6,%7}, {%8,%9}, {%0,%1,%2,%3};"
                         : "+f"(acc[nt][0]), "+f"(acc[nt][1]),
                           "+f"(acc[nt][2]), "+f"(acc[nt][3])
                         : "r"(a0), "r"(a1), "r"(a2), "r"(a3), "r"(b0), "r"(b1));
        }
    }
}

#define ZACC(acc) do { _Pragma("unroll") for (int _n = 0; _n < 8; _n++) \
    { acc[_n][0]=0.f; acc[_n][1]=0.f; acc[_n][2]=0.f; acc[_n][3]=0.f; } } while (0)

#define STAGE_B(Bs, ch) do { __syncthreads();                                  \
    for (int _it = 0; _it < 16; _it++) {                                       \
        int _i = _it * 256 + tid;                                              \
        *(float4*)&(Bs)[(_i >> 5) * AP + (_i & 31) * 4] =                      \
            *(const float4*)&d_Bw[(ch) * 16384 + _i * 4];                      \
    } __syncthreads(); } while (0)

// ---------------- prep kernels ----------------
__global__ void gate_kernel(const float* __restrict__ pos_enc, const float* __restrict__ Wg,
                            const float* __restrict__ bg) {
    int p = blockIdx.x, j = threadIdx.x;
    __shared__ float pe[PD];
    if (j < PD) pe[j] = pos_enc[p * PD + j];
    __syncthreads();
    float acc = bg[j];
#pragma unroll
    for (int k = 0; k < PD; k++) acc = fmaf(pe[k], Wg[k * HD + j], acc);
    d_gate[p * HD + j] = 2.0f / (1.0f + expf(-acc));
}

__global__ void init_h(const int* __restrict__ xidx, const float* __restrict__ sel,
                       const float* __restrict__ emb) {
    int v = blockIdx.x, j = threadIdx.x;
    float val = (j < VEMB) ? emb[xidx[v] * VEMB + j] : sel[v * 32 + (j - VEMB)];
    d_h0[v * HD + j] = val;
    d_h[v * HD + j]  = val;
}

__global__ void zero_cnt() {
    int i = blockIdx.x * blockDim.x + threadIdx.x;
    if (i < NT * NN) d_cntT[i] = 0.0f;
}
__global__ void cnt_kernel(const int* __restrict__ dst, const int* __restrict__ etype) {
    int e = blockIdx.x * blockDim.x + threadIdx.x;
    if (e < EE) atomicAdd(&d_cntT[etype[e] * NN + dst[e]], 1.0f);
}
__global__ void invden_kernel() {
    int v = blockIdx.x * blockDim.x + threadIdx.x;
    if (v < NN) {
        float t = d_cntT[v] + d_cntT[NN + v] + d_cntT[2 * NN + v];
        d_invden[v] = 1.0f / fmaxf(t, 1.0f);
    }
}

// chunks (row-major [k 128][n 128], tf32-rounded):
// 0..2: Wt[t]           B[k][j] = Wt[t][k][j]
// 3..5: Wih r/z/n       B[k][o] = Wih[(g*128+o)][k]
// 6..8: Whh r/z/n       B[k][o] = Whh[(g*128+o)][k]
// 9:    W1 rows 0..127  B[k][j] = W1[k][j]
// 10:   W1 rows 128..   B[k][j] = W1[128+k][j]
__global__ void bprep(const float* __restrict__ Wt, const float* __restrict__ Wih,
                      const float* __restrict__ Whh, const float* __restrict__ W1) {
    int c = blockIdx.x;
    for (int i = threadIdx.x; i < 16384; i += blockDim.x) {
        int k = i >> 7, n = i & 127;
        float v;
        if      (c < 3)  v = Wt[c * 16384 + k * HD + n];
        else if (c < 6)  v = Wih[((c - 3) * 128 + n) * HD + k];
        else if (c < 9)  v = Whh[((c - 6) * 128 + n) * HD + k];
        else if (c == 9) v = W1[k * HD + n];
        else             v = W1[(128 + k) * HD + n];
        d_Bw[c * 16384 + i] = __uint_as_float(to_tf32(v));
    }
}

// ---------------- per-iteration kernels ----------------
__global__ void zero_u() {
    int i = blockIdx.x * blockDim.x + threadIdx.x;
    const int n4 = NT * NN * HD / 4;
    if (i < n4) ((float4*)d_u)[i] = make_float4(0.f, 0.f, 0.f, 0.f);
}

__global__ void scatter_kernel(const int* __restrict__ src, const int* __restrict__ dst,
                               const int* __restrict__ etype, const int* __restrict__ epos) {
    int e = (blockIdx.x * blockDim.x + threadIdx.x) >> 5;
    int lane = threadIdx.x & 31;
    if (e >= EE) return;
    int s = src[e], d = dst[e], t = etype[e], p = epos[e];
    float4 hv = *(const float4*)&d_h[s * HD + lane * 4];
    float4 gv = *(const float4*)&d_gate[p * HD + lane * 4];
    float* base = &d_u[(t * NN + d) * HD + lane * 4];
    atomicAdd(base + 0, hv.x * gv.x);
    atomicAdd(base + 1, hv.y * gv.y);
    atomicAdd(base + 2, hv.z * gv.z);
    atomicAdd(base + 3, hv.w * gv.w);
}

// fused iteration: agg GEMM (+scale/bias) + GRU GEMMs + GRU epilogue, 64-node tile
// smem floats: As 0..8448 | Hs 8448..16896 | Bs 16896..33792 | sbt 33792 |
//              sbih 34176 | sbhh 34560 | scnt 34944 (3*64) | sinv 35136 (64)
#define SMEM_IT (35200 * 4)

__global__ __launch_bounds__(256, 1) void iter_kernel(const float* __restrict__ bih,
                                                      const float* __restrict__ bhh,
                                                      const float* __restrict__ bt) {
    extern __shared__ float sm[];
    float* As   = sm;
    float* Hs   = sm + 8448;
    float* Bs   = sm + 16896;
    float* sbt  = sm + 33792;
    float* sbih = sm + 34176;
    float* sbhh = sm + 34560;
    float* scnt = sm + 34944;
    float* sinv = sm + 35136;

    int tid = threadIdx.x, lane = tid & 31, wid = tid >> 5;
    int g = lane >> 2, tig = lane & 3;
    int r0 = (wid & 3) * 16, c0 = (wid >> 2) * 64;
    int tile0 = blockIdx.x * 64;

    for (int i = tid; i < 384; i += 256) { sbt[i] = bt[i]; sbih[i] = bih[i]; sbhh[i] = bhh[i]; }
    if (tid < 64) {
        int v = tile0 + tid;
        bool ok = v < NN;
        sinv[tid]       = ok ? d_invden[v] : 0.f;
        scnt[tid]       = ok ? d_cntT[v] : 0.f;
        scnt[64 + tid]  = ok ? d_cntT[NN + v] : 0.f;
        scnt[128 + tid] = ok ? d_cntT[2 * NN + v] : 0.f;
    }
    // stage h (exact fp32)
    for (int it = 0; it < 8; it++) {
        int i = it * 256 + tid, r = i >> 5, q = i & 31, v = tile0 + r;
        float4 val = (v < NN) ? *(const float4*)&d_h[v * HD + q * 4]
                              : make_float4(0.f, 0.f, 0.f, 0.f);
        *(float4*)&Hs[r * AP + q * 4] = val;
    }

    float acc[8][4];
    ZACC(acc);
    // ---- stage 1: acc = sum_t u_t @ Wt[t] ----
    for (int t = 0; t < NT; t++) {
        __syncthreads();
        for (int it = 0; it < 8; it++) {
            int i = it * 256 + tid, r = i >> 5, q = i & 31, v = tile0 + r;
            float4 val = (v < NN) ? *(const float4*)&d_u[(t * NN + v) * HD + q * 4]
                                  : make_float4(0.f, 0.f, 0.f, 0.f);
            uint4 o;
            o.x = to_tf32(val.x); o.y = to_tf32(val.y);
            o.z = to_tf32(val.z); o.w = to_tf32(val.w);
            *(uint4*)&As[r * AP + q * 4] = o;
        }
        for (int it = 0; it < 16; it++) {
            int i = it * 256 + tid;
            *(float4*)&Bs[(i >> 5) * AP + (i & 31) * 4] = *(const float4*)&d_Bw[t * 16384 + i * 4];
        }
        __syncthreads();
        gemm_tile<false>(As, Bs, r0, c0, g, tig, acc);
    }
    __syncthreads();
    // epilogue: agg = (acc + cnt_t*bt_t)*inv  -> As (tf32 bits)
#pragma unroll
    for (int nt = 0; nt < 8; nt++)
#pragma unroll
        for (int i = 0; i < 4; i++) {
            int row = r0 + g + (i >> 1) * 8;
            int col = c0 + nt * 8 + 2 * tig + (i & 1);
            float a = acc[nt][i] + scnt[row] * sbt[col] + scnt[64 + row] * sbt[128 + col]
                    + scnt[128 + row] * sbt[256 + col];
            As[row * AP + col] = __uint_as_float(to_tf32(a * sinv[row]));
        }
    __syncthreads();

    // ---- stage 2: GRU ----
    float rr[8][4];

    // r = sigma(agg@Wih_r + h@Whh_r + b)
    ZACC(acc);
    STAGE_B(Bs, 3); gemm_tile<false>(As, Bs, r0, c0, g, tig, acc);
    STAGE_B(Bs, 6); gemm_tile<true>(Hs, Bs, r0, c0, g, tig, acc);
#pragma unroll
    for (int nt = 0; nt < 8; nt++)
#pragma unroll
        for (int i = 0; i < 4; i++) {
            int col = c0 + nt * 8 + 2 * tig + (i & 1);
            rr[nt][i] = sigf(acc[nt][i] + sbih[col] + sbhh[col]);
        }

    // rghn = r * (h@Whh_n + bhh_n)
    ZACC(acc);
    STAGE_B(Bs, 8); gemm_tile<true>(Hs, Bs, r0, c0, g, tig, acc);
#pragma unroll
    for (int nt = 0; nt < 8; nt++)
#pragma unroll
        for (int i = 0; i < 4; i++) {
            int col = c0 + nt * 8 + 2 * tig + (i & 1);
            rr[nt][i] = rr[nt][i] * (acc[nt][i] + sbhh[256 + col]);
        }

    // n = tanh(agg@Wih_n + bih_n + rghn)
    ZACC(acc);
    STAGE_B(Bs, 5); gemm_tile<false>(As, Bs, r0, c0, g, tig, acc);
#pragma unroll
    for (int nt = 0; nt < 8; nt++)
#pragma unroll
        for (int i = 0; i < 4; i++) {
            int col = c0 + nt * 8 + 2 * tig + (i & 1);
            rr[nt][i] = tanhf(acc[nt][i] + sbih[256 + col] + rr[nt][i]);
        }

    // z = sigma(agg@Wih_z + h@Whh_z + b);  h_new = (1-z)*n + z*h_prev
    ZACC(acc);
    STAGE_B(Bs, 4); gemm_tile<false>(As, Bs, r0, c0, g, tig, acc);
    STAGE_B(Bs, 7); gemm_tile<true>(Hs, Bs, r0, c0, g, tig, acc);
#pragma unroll
    for (int nt = 0; nt < 8; nt++)
#pragma unroll
        for (int i2 = 0; i2 < 2; i2++) {   // i2 = row half
            int row = r0 + g + i2 * 8;
            int v = tile0 + row;
            if (v < NN) {
                int colb = c0 + nt * 8 + 2 * tig;
                float z0 = sigf(acc[nt][i2 * 2 + 0] + sbih[128 + colb] + sbhh[128 + colb]);
                float z1 = sigf(acc[nt][i2 * 2 + 1] + sbih[129 + colb] + sbhh[129 + colb]);
                float hp0 = Hs[row * AP + colb], hp1 = Hs[row * AP + colb + 1];
                float2 o;
                o.x = (1.f - z0) * rr[nt][i2 * 2 + 0] + z0 * hp0;
                o.y = (1.f - z1) * rr[nt][i2 * 2 + 1] + z1 * hp1;
                *(float2*)&d_h[v * HD + colb] = o;
            }
        }
}

// ---------------- readout ----------------
// smem floats: As 0..8448 | Bs 8448..25344 | sb1 25344 | sW2 25472 | sred 25600 (2*64)
#define SMEM_RO (25728 * 4)

__global__ __launch_bounds__(256, 1) void readout_tc(const float* __restrict__ b1,
                                                     const float* __restrict__ W2,
                                                     const float* __restrict__ b2,
                                                     float* __restrict__ out) {
    extern __shared__ float sm[];
    float* As   = sm;
    float* Bs   = sm + 8448;
    float* sb1  = sm + 25344;
    float* sW2  = sm + 25472;
    float* sred = sm + 25600;

    int tid = threadIdx.x, lane = tid & 31, wid = tid >> 5;
    int g = lane >> 2, tig = lane & 3;
    int r0 = (wid & 3) * 16, c0 = (wid >> 2) * 64;
    int tile0 = blockIdx.x * 64;

    if (tid < 128) { sb1[tid] = b1[tid]; sW2[tid] = W2[tid]; sred[tid] = 0.f; }

    float acc[8][4];
    ZACC(acc);
    for (int s = 0; s < 2; s++) {
        __syncthreads();
        const float* hsrc = s ? d_h0 : d_h;
        for (int it = 0; it < 8; it++) {
            int i = it * 256 + tid, r = i >> 5, q = i & 31, v = tile0 + r;
            float4 val = (v < NN) ? *(const float4*)&hsrc[v * HD + q * 4]
                                  : make_float4(0.f, 0.f, 0.f, 0.f);
            uint4 o;
            o.x = to_tf32(val.x); o.y = to_tf32(val.y);
            o.z = to_tf32(val.z); o.w = to_tf32(val.w);
            *(uint4*)&As[r * AP + q * 4] = o;
        }
        for (int it = 0; it < 16; it++) {
            int i = it * 256 + tid;
            *(float4*)&Bs[(i >> 5) * AP + (i & 31) * 4] =
                *(const float4*)&d_Bw[(9 + s) * 16384 + i * 4];
        }
        __syncthreads();
        gemm_tile<false>(As, Bs, r0, c0, g, tig, acc);
    }
    // p = sum_cols relu(acc + b1) * W2
    float p0 = 0.f, p1 = 0.f;
#pragma unroll
    for (int nt = 0; nt < 8; nt++) {
        int colb = c0 + nt * 8 + 2 * tig;
        p0 += fmaxf(acc[nt][0] + sb1[colb],     0.f) * sW2[colb];
        p0 += fmaxf(acc[nt][1] + sb1[colb + 1], 0.f) * sW2[colb + 1];
        p1 += fmaxf(acc[nt][2] + sb1[colb],     0.f) * sW2[colb];
        p1 += fmaxf(acc[nt][3] + sb1[colb + 1], 0.f) * sW2[colb + 1];
    }
    p0 += __shfl_down_sync(0xffffffffu, p0, 1, 4);
    p0 += __shfl_down_sync(0xffffffffu, p0, 2, 4);
    p1 += __shfl_down_sync(0xffffffffu, p1, 1, 4);
    p1 += __shfl_down_sync(0xffffffffu, p1, 2, 4);
    if (tig == 0) {
        int wn = wid >> 2;
        sred[wn * 64 + r0 + g]     = p0;
        sred[wn * 64 + r0 + g + 8] = p1;
    }
    __syncthreads();
    if (tid < 64) {
        int v = tile0 + tid;
        if (v < NN) out[v] = sred[tid] + sred[64 + tid] + b2[0];
    }
}

// ---------------- launch ----------------
extern "C" void kernel_launch(void* const* d_in, const int* in_sizes, int n_in,
                              void* d_out, int out_size) {
    const int*   xidx    = (const int*)d_in[0];
    const float* sel     = (const float*)d_in[1];
    const int*   eidx    = (const int*)d_in[2];
    const int*   etype   = (const int*)d_in[3];
    const int*   epos    = (const int*)d_in[4];
    const float* emb     = (const float*)d_in[5];
    const float* pos_enc = (const float*)d_in[6];
    const float* Wg      = (const float*)d_in[7];
    const float* bg      = (const float*)d_in[8];
    const float* Wt      = (const float*)d_in[9];
    const float* bt      = (const float*)d_in[10];
    const float* Wih     = (const float*)d_in[11];
    const float* Whh     = (const float*)d_in[12];
    const float* bih     = (const float*)d_in[13];
    const float* bhh     = (const float*)d_in[14];
    const float* W1      = (const float*)d_in[15];
    const float* b1      = (const float*)d_in[16];
    const float* W2      = (const float*)d_in[17];
    const float* b2      = (const float*)d_in[18];
    const int* src = eidx;
    const int* dst = eidx + EE;
    float* out = (float*)d_out;

    cudaFuncSetAttribute(iter_kernel, cudaFuncAttributeMaxDynamicSharedMemorySize, SMEM_IT);
    cudaFuncSetAttribute(readout_tc, cudaFuncAttributeMaxDynamicSharedMemorySize, SMEM_RO);

    gate_kernel<<<NPOS, HD>>>(pos_enc, Wg, bg);
    init_h<<<NN, HD>>>(xidx, sel, emb);
    zero_cnt<<<(NT * NN + 255) / 256, 256>>>();
    cnt_kernel<<<(EE + 255) / 256, 256>>>(dst, etype);
    invden_kernel<<<(NN + 255) / 256, 256>>>();
    bprep<<<11, 256>>>(Wt, Wih, Whh, W1);

    for (int it = 0; it < 6; it++) {
        zero_u<<<(NT * NN * HD / 4 + 255) / 256, 256>>>();
        scatter_kernel<<<(EE * 32 + 255) / 256, 256>>>(src, dst, etype, epos);
        iter_kernel<<<NT64, 256, SMEM_IT>>>(bih, bhh, bt);
    }
    readout_tc<<<NT64, 256, SMEM_RO>>>(b1, W2, b2, out);
}

// round 5
// speedup vs baseline: 2.4916x; 1.3203x over previous
#include <cuda_runtime.h>
#include <cstdint>

#define NN   100000
#define EE   640000
#define HD   128
#define NT   3
#define PD   64
#define NPOS 513
#define VEMB 96
#define NT64 1563          // ceil(100000/64)
#define AP   132           // smem pitch for A/H tiles (floats)

// ---------------- device scratch ----------------
static __device__ float d_hA[NN * HD];
static __device__ float d_hB[NN * HD];
static __device__ float d_h0[NN * HD];
static __device__ float d_gate[NPOS * HD];
static __device__ float d_cntT[NT * NN];
static __device__ float d_invden[NN];
static __device__ int   d_degi[NN];
static __device__ int   d_fill[NN];
static __device__ int   d_rowtmp[NN];
static __device__ int   d_rowp[NN];
static __device__ int   d_bsum[98];
static __device__ unsigned d_epk[EE];
static __device__ float d_Bw[11 * 16384];   // packed-pair tf32 weight chunks

// ---------------- helpers ----------------
__device__ __forceinline__ unsigned to_tf32(float f) {
    unsigned r; asm("cvt.rna.tf32.f32 %0, %1;" : "=r"(r) : "f"(f)); return r;
}
__device__ __forceinline__ float sigf(float x) { return 1.0f / (1.0f + expf(-x)); }

// warp tf32 MMA, packed-pair B: Bp[ks*1024 + n*8 + tig*2 + j] = B[ks*8+tig+4j][n]
template<bool CVTA>
__device__ __forceinline__ void gemm_p(const float* __restrict__ Amat,
                                       const float* __restrict__ Bp,
                                       int r0, int c0, int g, int tig,
                                       float acc[8][4]) {
#pragma unroll 4
    for (int ks = 0; ks < 16; ks++) {
        const float* ap = Amat + (r0 + g) * AP + ks * 8 + tig;
        float f0 = ap[0], f1 = ap[8 * AP], f2 = ap[4], f3 = ap[8 * AP + 4];
        unsigned a0, a1, a2, a3;
        if (CVTA) {
            a0 = to_tf32(f0); a1 = to_tf32(f1); a2 = to_tf32(f2); a3 = to_tf32(f3);
        } else {
            a0 = __float_as_uint(f0); a1 = __float_as_uint(f1);
            a2 = __float_as_uint(f2); a3 = __float_as_uint(f3);
        }
        const float2* bp = (const float2*)(Bp + ks * 1024) + tig;
#pragma unroll
        for (int nt = 0; nt < 8; nt++) {
            float2 b = bp[(c0 + g + nt * 8) * 4];
            unsigned b0 = __float_as_uint(b.x), b1 = __float_as_uint(b.y);
            asm volatile("mma.sync.aligned.m16n8k8.row.col.f32.tf32.tf32.f32 "
                         "{%0,%1,%2,%3}, {%4,%5,%6,%7}, {%8,%9}, {%0,%1,%2,%3};"
                         : "+f"(acc[nt][0]), "+f"(acc[nt][1]),
                           "+f"(acc[nt][2]), "+f"(acc[nt][3])
                         : "r"(a0), "r"(a1), "r"(a2), "r"(a3), "r"(b0), "r"(b1));
        }
    }
}

#define ZACC(acc) do { _Pragma("unroll") for (int _n = 0; _n < 8; _n++) \
    { acc[_n][0]=0.f; acc[_n][1]=0.f; acc[_n][2]=0.f; acc[_n][3]=0.f; } } while (0)

#define STAGE_B(Bs, ch) do { __syncthreads();                                  \
    for (int _it = 0; _it < 16; _it++) {                                       \
        int _i = _it * 256 + tid;                                              \
        *(float4*)&(Bs)[_i * 4] = *(const float4*)&d_Bw[(ch) * 16384 + _i * 4];\
    } __syncthreads(); } while (0)

// ---------------- prep kernels ----------------
__global__ void gate_kernel(const float* __restrict__ pos_enc, const float* __restrict__ Wg,
                            const float* __restrict__ bg) {
    int p = blockIdx.x, j = threadIdx.x;
    __shared__ float pe[PD];
    if (j < PD) pe[j] = pos_enc[p * PD + j];
    __syncthreads();
    float acc = bg[j];
#pragma unroll
    for (int k = 0; k < PD; k++) acc = fmaf(pe[k], Wg[k * HD + j], acc);
    d_gate[p * HD + j] = 2.0f / (1.0f + expf(-acc));
}

__global__ void init_h(const int* __restrict__ xidx, const float* __restrict__ sel,
                       const float* __restrict__ emb) {
    int v = blockIdx.x, j = threadIdx.x;
    float val = (j < VEMB) ? emb[xidx[v] * VEMB + j] : sel[v * 32 + (j - VEMB)];
    d_h0[v * HD + j] = val;
    d_hA[v * HD + j] = val;
}

__global__ void zero_misc() {
    int i = blockIdx.x * blockDim.x + threadIdx.x;
    if (i < NT * NN) d_cntT[i] = 0.0f;
    if (i < NN) { d_degi[i] = 0; d_fill[i] = 0; }
}
__global__ void cnt_kernel(const int* __restrict__ dst, const int* __restrict__ etype) {
    int e = blockIdx.x * blockDim.x + threadIdx.x;
    if (e < EE) {
        atomicAdd(&d_cntT[etype[e] * NN + dst[e]], 1.0f);
        atomicAdd(&d_degi[dst[e]], 1);
    }
}
__global__ void invden_kernel() {
    int v = blockIdx.x * blockDim.x + threadIdx.x;
    if (v < NN) d_invden[v] = 1.0f / fmaxf((float)d_degi[v], 1.0f);
}

__global__ void scanA() {
    __shared__ int s[1024];
    int b = blockIdx.x, t = threadIdx.x;
    int i = b * 1024 + t;
    s[t] = (i < NN) ? d_degi[i] : 0;
    __syncthreads();
#pragma unroll
    for (int off = 1; off < 1024; off <<= 1) {
        int x = (t >= off) ? s[t - off] : 0;
        __syncthreads();
        s[t] += x;
        __syncthreads();
    }
    if (i < NN) d_rowtmp[i] = s[t];
    if (t == 1023) d_bsum[b] = s[1023];
}
__global__ void scanB() {
    if (threadIdx.x == 0) {
        int run = 0;
        for (int b = 0; b < 98; b++) { int x = d_bsum[b]; d_bsum[b] = run; run += x; }
    }
}
__global__ void scanC() {
    int i = blockIdx.x * blockDim.x + threadIdx.x;
    if (i < NN) d_rowp[i] = d_rowtmp[i] - d_degi[i] + d_bsum[i >> 10];
}
__global__ void fill_kernel(const int* __restrict__ src, const int* __restrict__ dst,
                            const int* __restrict__ etype, const int* __restrict__ epos) {
    int e = blockIdx.x * blockDim.x + threadIdx.x;
    if (e < EE) {
        int dv = dst[e];
        int slot = d_rowp[dv] + atomicAdd(&d_fill[dv], 1);
        d_epk[slot] = (unsigned)src[e] | ((unsigned)epos[e] << 17) | ((unsigned)etype[e] << 27);
    }
}

// packed-pair chunk layout: d_Bw[c*16384 + ks*1024 + n*8 + tig*2 + j] = tf32(W_c[ks*8+tig+4j][n])
// chunks: 0..2 Wt[t]; 3..5 Wih r/z/n (W[k][o]=Wih[o][k]); 6..8 Whh r/z/n; 9..10 W1 halves
__global__ void bprep(const float* __restrict__ Wt, const float* __restrict__ Wih,
                      const float* __restrict__ Whh, const float* __restrict__ W1) {
    int c = blockIdx.x;
    for (int i = threadIdx.x; i < 16384; i += blockDim.x) {
        int j = i & 1, tig = (i >> 1) & 3, n = (i >> 3) & 127, ks = i >> 10;
        int k = ks * 8 + tig + 4 * j;
        float v;
        if      (c < 3)  v = Wt[c * 16384 + k * HD + n];
        else if (c < 6)  v = Wih[((c - 3) * 128 + n) * HD + k];
        else if (c < 9)  v = Whh[((c - 6) * 128 + n) * HD + k];
        else if (c == 9) v = W1[k * HD + n];
        else             v = W1[(128 + k) * HD + n];
        d_Bw[c * 16384 + i] = __uint_as_float(to_tf32(v));
    }
}

// ---------------- fused iteration kernel ----------------
// smem floats: A0 0 | A1 8448 | A2 16896 | Hs 25344 | Bs 33792(16384) |
//              sbt 50176 | sbih 50560 | sbhh 50944 | scnt 51328(192) | sinv 51520(64)
#define OFF_H   25344
#define OFF_B   33792
#define OFF_BT  50176
#define OFF_BIH 50560
#define OFF_BHH 50944
#define OFF_CNT 51328
#define OFF_INV 51520
#define SMEM_IT (51584 * 4)

__global__ __launch_bounds__(256, 1) void iter_kernel(int dir,
                                                      const float* __restrict__ bih,
                                                      const float* __restrict__ bhh,
                                                      const float* __restrict__ bt) {
    extern __shared__ float sm[];
    const float* hin = dir ? d_hB : d_hA;
    float*       hout = dir ? d_hA : d_hB;
    float* Hs   = sm + OFF_H;
    float* Bs   = sm + OFF_B;
    float* sbt  = sm + OFF_BT;
    float* sbih = sm + OFF_BIH;
    float* sbhh = sm + OFF_BHH;
    float* scnt = sm + OFF_CNT;   // cnt_t * invden
    float* sinv = sm + OFF_INV;

    int tid = threadIdx.x, lane = tid & 31, wid = tid >> 5;
    int g = lane >> 2, tig = lane & 3;
    int r0 = (wid & 3) * 16, c0 = (wid >> 2) * 64;
    int tile0 = blockIdx.x * 64;

    for (int i = tid; i < 384; i += 256) { sbt[i] = bt[i]; sbih[i] = bih[i]; sbhh[i] = bhh[i]; }
    if (tid < 64) {
        int v = tile0 + tid;
        bool ok = v < NN;
        float inv = ok ? d_invden[v] : 0.f;
        sinv[tid]       = inv;
        scnt[tid]       = ok ? d_cntT[v] * inv : 0.f;
        scnt[64 + tid]  = ok ? d_cntT[NN + v] * inv : 0.f;
        scnt[128 + tid] = ok ? d_cntT[2 * NN + v] * inv : 0.f;
    }
    // stage h_prev (exact fp32)
    for (int it = 0; it < 8; it++) {
        int i = it * 256 + tid, r = i >> 5, q = i & 31, v = tile0 + r;
        float4 val = (v < NN) ? *(const float4*)&hin[v * HD + q * 4]
                              : make_float4(0.f, 0.f, 0.f, 0.f);
        *(float4*)&Hs[r * AP + q * 4] = val;
    }
    __syncthreads();

    // ---- CSR gather: A_t[r][:] = invden * sum_{e->r, type t} h_in[src] * gate[pos] ----
    for (int r = wid; r < 64; r += 8) {
        int v = tile0 + r;
        float4 a0 = make_float4(0.f, 0.f, 0.f, 0.f), a1 = a0, a2 = a0;
        if (v < NN) {
            int st = d_rowp[v], dg = d_degi[v];
            for (int e = 0; e < dg; e += 4) {
                int m = dg - e;
                unsigned wd[4];
                float4 hv[4], gv[4];
#pragma unroll
                for (int i = 0; i < 4; i++)
                    wd[i] = (i < m) ? d_epk[st + e + i] : 0xFFFFFFFFu;
#pragma unroll
                for (int i = 0; i < 4; i++) {
                    if (wd[i] != 0xFFFFFFFFu) {
                        int s = wd[i] & 0x1FFFF, p = (wd[i] >> 17) & 0x3FF;
                        hv[i] = *(const float4*)&hin[s * HD + lane * 4];
                        gv[i] = *(const float4*)&d_gate[p * HD + lane * 4];
                    }
                }
#pragma unroll
                for (int i = 0; i < 4; i++) {
                    if (wd[i] != 0xFFFFFFFFu) {
                        int t = wd[i] >> 27;
                        float4 mv;
                        mv.x = hv[i].x * gv[i].x; mv.y = hv[i].y * gv[i].y;
                        mv.z = hv[i].z * gv[i].z; mv.w = hv[i].w * gv[i].w;
                        if (t == 0) { a0.x += mv.x; a0.y += mv.y; a0.z += mv.z; a0.w += mv.w; }
                        else if (t == 1) { a1.x += mv.x; a1.y += mv.y; a1.z += mv.z; a1.w += mv.w; }
                        else { a2.x += mv.x; a2.y += mv.y; a2.z += mv.z; a2.w += mv.w; }
                    }
                }
            }
            float iv = sinv[r];
            a0.x *= iv; a0.y *= iv; a0.z *= iv; a0.w *= iv;
            a1.x *= iv; a1.y *= iv; a1.z *= iv; a1.w *= iv;
            a2.x *= iv; a2.y *= iv; a2.z *= iv; a2.w *= iv;
        }
        uint4 o;
        o.x = to_tf32(a0.x); o.y = to_tf32(a0.y); o.z = to_tf32(a0.z); o.w = to_tf32(a0.w);
        *(uint4*)&sm[0 * 8448 + r * AP + lane * 4] = o;
        o.x = to_tf32(a1.x); o.y = to_tf32(a1.y); o.z = to_tf32(a1.z); o.w = to_tf32(a1.w);
        *(uint4*)&sm[1 * 8448 + r * AP + lane * 4] = o;
        o.x = to_tf32(a2.x); o.y = to_tf32(a2.y); o.z = to_tf32(a2.z); o.w = to_tf32(a2.w);
        *(uint4*)&sm[2 * 8448 + r * AP + lane * 4] = o;
    }

    // ---- stage 1: acc = sum_t A_t @ Wt[t]  (A pre-scaled by invden) ----
    float acc[8][4];
    ZACC(acc);
    for (int t = 0; t < NT; t++) {
        STAGE_B(Bs, t);
        gemm_p<false>(sm + t * 8448, Bs, r0, c0, g, tig, acc);
    }
    __syncthreads();
    // epilogue: agg = acc + sum_t (cnt_t*inv)*bt_t  -> A0 (tf32 bits)
#pragma unroll
    for (int nt = 0; nt < 8; nt++)
#pragma unroll
        for (int i = 0; i < 4; i++) {
            int row = r0 + g + (i >> 1) * 8;
            int col = c0 + nt * 8 + 2 * tig + (i & 1);
            float a = acc[nt][i] + scnt[row] * sbt[col] + scnt[64 + row] * sbt[128 + col]
                    + scnt[128 + row] * sbt[256 + col];
            sm[row * AP + col] = __uint_as_float(to_tf32(a));
        }
    __syncthreads();

    // ---- stage 2: GRU ----
    float rr[8][4];

    // r = sigma(agg@Wih_r + h@Whh_r + b)
    ZACC(acc);
    STAGE_B(Bs, 3); gemm_p<false>(sm, Bs, r0, c0, g, tig, acc);
    STAGE_B(Bs, 6); gemm_p<true>(Hs, Bs, r0, c0, g, tig, acc);
#pragma unroll
    for (int nt = 0; nt < 8; nt++)
#pragma unroll
        for (int i = 0; i < 4; i++) {
            int col = c0 + nt * 8 + 2 * tig + (i & 1);
            rr[nt][i] = sigf(acc[nt][i] + sbih[col] + sbhh[col]);
        }

    // rghn = r * (h@Whh_n + bhh_n)
    ZACC(acc);
    STAGE_B(Bs, 8); gemm_p<true>(Hs, Bs, r0, c0, g, tig, acc);
#pragma unroll
    for (int nt = 0; nt < 8; nt++)
#pragma unroll
        for (int i = 0; i < 4; i++) {
            int col = c0 + nt * 8 + 2 * tig + (i & 1);
            rr[nt][i] = rr[nt][i] * (acc[nt][i] + sbhh[256 + col]);
        }

    // n = tanh(agg@Wih_n + bih_n + rghn)
    ZACC(acc);
    STAGE_B(Bs, 5); gemm_p<false>(sm, Bs, r0, c0, g, tig, acc);
#pragma unroll
    for (int nt = 0; nt < 8; nt++)
#pragma unroll
        for (int i = 0; i < 4; i++) {
            int col = c0 + nt * 8 + 2 * tig + (i & 1);
            rr[nt][i] = tanhf(acc[nt][i] + sbih[256 + col] + rr[nt][i]);
        }

    // z = sigma(agg@Wih_z + h@Whh_z + b);  h_new = (1-z)*n + z*h_prev
    ZACC(acc);
    STAGE_B(Bs, 4); gemm_p<false>(sm, Bs, r0, c0, g, tig, acc);
    STAGE_B(Bs, 7); gemm_p<true>(Hs, Bs, r0, c0, g, tig, acc);
#pragma unroll
    for (int nt = 0; nt < 8; nt++)
#pragma unroll
        for (int i2 = 0; i2 < 2; i2++) {
            int row = r0 + g + i2 * 8;
            int v = tile0 + row;
            if (v < NN) {
                int colb = c0 + nt * 8 + 2 * tig;
                float z0 = sigf(acc[nt][i2 * 2 + 0] + sbih[128 + colb] + sbhh[128 + colb]);
                float z1 = sigf(acc[nt][i2 * 2 + 1] + sbih[129 + colb] + sbhh[129 + colb]);
                float hp0 = Hs[row * AP + colb], hp1 = Hs[row * AP + colb + 1];
                float2 o;
                o.x = (1.f - z0) * rr[nt][i2 * 2 + 0] + z0 * hp0;
                o.y = (1.f - z1) * rr[nt][i2 * 2 + 1] + z1 * hp1;
                *(float2*)&hout[v * HD + colb] = o;
            }
        }
}

// ---------------- readout ----------------
// smem floats: As 0..8448 | Bs 8448(16384) | sb1 24832 | sW2 24960 | sred 25088(128)
#define SMEM_RO (25216 * 4)

__global__ __launch_bounds__(256, 1) void readout_tc(const float* __restrict__ b1,
                                                     const float* __restrict__ W2,
                                                     const float* __restrict__ b2,
                                                     float* __restrict__ out) {
    extern __shared__ float sm[];
    float* As   = sm;
    float* Bs   = sm + 8448;
    float* sb1  = sm + 24832;
    float* sW2  = sm + 24960;
    float* sred = sm + 25088;

    int tid = threadIdx.x, lane = tid & 31, wid = tid >> 5;
    int g = lane >> 2, tig = lane & 3;
    int r0 = (wid & 3) * 16, c0 = (wid >> 2) * 64;
    int tile0 = blockIdx.x * 64;

    if (tid < 128) { sb1[tid] = b1[tid]; sW2[tid] = W2[tid]; sred[tid] = 0.f; }

    float acc[8][4];
    ZACC(acc);
    for (int s = 0; s < 2; s++) {
        __syncthreads();
        const float* hsrc = s ? d_h0 : d_hA;
        for (int it = 0; it < 8; it++) {
            int i = it * 256 + tid, r = i >> 5, q = i & 31, v = tile0 + r;
            float4 val = (v < NN) ? *(const float4*)&hsrc[v * HD + q * 4]
                                  : make_float4(0.f, 0.f, 0.f, 0.f);
            uint4 o;
            o.x = to_tf32(val.x); o.y = to_tf32(val.y);
            o.z = to_tf32(val.z); o.w = to_tf32(val.w);
            *(uint4*)&As[r * AP + q * 4] = o;
        }
        for (int it = 0; it < 16; it++) {
            int i = it * 256 + tid;
            *(float4*)&Bs[i * 4] = *(const float4*)&d_Bw[(9 + s) * 16384 + i * 4];
        }
        __syncthreads();
        gemm_p<false>(As, Bs, r0, c0, g, tig, acc);
    }
    float p0 = 0.f, p1 = 0.f;
#pragma unroll
    for (int nt = 0; nt < 8; nt++) {
        int colb = c0 + nt * 8 + 2 * tig;
        p0 += fmaxf(acc[nt][0] + sb1[colb],     0.f) * sW2[colb];
        p0 += fmaxf(acc[nt][1] + sb1[colb + 1], 0.f) * sW2[colb + 1];
        p1 += fmaxf(acc[nt][2] + sb1[colb],     0.f) * sW2[colb];
        p1 += fmaxf(acc[nt][3] + sb1[colb + 1], 0.f) * sW2[colb + 1];
    }
    p0 += __shfl_down_sync(0xffffffffu, p0, 1, 4);
    p0 += __shfl_down_sync(0xffffffffu, p0, 2, 4);
    p1 += __shfl_down_sync(0xffffffffu, p1, 1, 4);
    p1 += __shfl_down_sync(0xffffffffu, p1, 2, 4);
    if (tig == 0) {
        int wn = wid >> 2;
        sred[wn * 64 + r0 + g]     = p0;
        sred[wn * 64 + r0 + g + 8] = p1;
    }
    __syncthreads();
    if (tid < 64) {
        int v = tile0 + tid;
        if (v < NN) out[v] = sred[tid] + sred[64 + tid] + b2[0];
    }
}

// ---------------- launch ----------------
extern "C" void kernel_launch(void* const* d_in, const int* in_sizes, int n_in,
                              void* d_out, int out_size) {
    const int*   xidx    = (const int*)d_in[0];
    const float* sel     = (const float*)d_in[1];
    const int*   eidx    = (const int*)d_in[2];
    const int*   etype   = (const int*)d_in[3];
    const int*   epos    = (const int*)d_in[4];
    const float* emb     = (const float*)d_in[5];
    const float* pos_enc = (const float*)d_in[6];
    const float* Wg      = (const float*)d_in[7];
    const float* bg      = (const float*)d_in[8];
    const float* Wt      = (const float*)d_in[9];
    const float* bt      = (const float*)d_in[10];
    const float* Wih     = (const float*)d_in[11];
    const float* Whh     = (const float*)d_in[12];
    const float* bih     = (const float*)d_in[13];
    const float* bhh     = (const float*)d_in[14];
    const float* W1      = (const float*)d_in[15];
    const float* b1      = (const float*)d_in[16];
    const float* W2      = (const float*)d_in[17];
    const float* b2      = (const float*)d_in[18];
    const int* src = eidx;
    const int* dst = eidx + EE;
    float* out = (float*)d_out;

    cudaFuncSetAttribute(iter_kernel, cudaFuncAttributeMaxDynamicSharedMemorySize, SMEM_IT);
    cudaFuncSetAttribute(readout_tc, cudaFuncAttributeMaxDynamicSharedMemorySize, SMEM_RO);

    gate_kernel<<<NPOS, HD>>>(pos_enc, Wg, bg);
    init_h<<<NN, HD>>>(xidx, sel, emb);
    zero_misc<<<(NT * NN + 255) / 256, 256>>>();
    cnt_kernel<<<(EE + 255) / 256, 256>>>(dst, etype);
    invden_kernel<<<(NN + 255) / 256, 256>>>();
    scanA<<<98, 1024>>>();
    scanB<<<1, 32>>>();
    scanC<<<(NN + 255) / 256, 256>>>();
    fill_kernel<<<(EE + 255) / 256, 256>>>(src, dst, etype, epos);
    bprep<<<11, 256>>>(Wt, Wih, Whh, W1);

    for (int it = 0; it < 6; it++)
        iter_kernel<<<NT64, 256, SMEM_IT>>>(it & 1, bih, bhh, bt);

    readout_tc<<<NT64, 256, SMEM_RO>>>(b1, W2, b2, out);
}

// round 6
// speedup vs baseline: 4.5108x; 1.8104x over previous
#include <cuda_runtime.h>
#include <cuda_fp16.h>
#include <cstdint>

#define NN   100000
#define EE   640000
#define HD   128
#define NT   3
#define PD   64
#define NPOS 513
#define VEMB 96
#define NT64 1563          // ceil(100000/64)
#define APW  68            // A/H tile pitch in 4B words (136 halves)

// ---------------- device scratch ----------------
static __device__ float d_hA[NN * HD];
static __device__ float d_hB[NN * HD];
static __device__ float d_h0[NN * HD];
static __device__ float d_gate[NPOS * HD];
static __device__ float d_cntT[NT * NN];
static __device__ float d_invden[NN];
static __device__ int   d_degi[NN];
static __device__ int   d_fill[NN];
static __device__ int   d_rowtmp[NN];
static __device__ int   d_rowp[NN];
static __device__ int   d_bsum[98];
static __device__ unsigned d_epk[EE];
static __device__ unsigned d_Bh[11 * 8192];   // fp16 packed-pair weight chunks (32KB each)

// ---------------- helpers ----------------
__device__ __forceinline__ float sigf(float x) { return 1.0f / (1.0f + expf(-x)); }
__device__ __forceinline__ unsigned packh2(float lo, float hi) {
    __half2 h = __floats2half2_rn(lo, hi);   // .x = lo half
    return *(unsigned*)&h;
}

// fp16 warp MMA m16n8k16 over K=128: A = half tile (word ptr, pitch APW),
// B = packed chunk in smem: uint idx = ks*1024 + n*8 + tig*2 + j
__device__ __forceinline__ void gemm_h(const unsigned* __restrict__ Aw,
                                       const unsigned* __restrict__ Bs,
                                       int r0, int c0, int g, int tig,
                                       float acc[8][4]) {
#pragma unroll
    for (int ks = 0; ks < 8; ks++) {
        const unsigned* ap = Aw + (r0 + g) * APW + ks * 8 + tig;
        unsigned a0 = ap[0], a1 = ap[8 * APW], a2 = ap[4], a3 = ap[8 * APW + 4];
        const uint2* bp = (const uint2*)Bs + ks * 512 + (c0 + g) * 4 + tig;
#pragma unroll
        for (int nt = 0; nt < 8; nt++) {
            uint2 b = bp[nt * 32];
            asm volatile("mma.sync.aligned.m16n8k16.row.col.f32.f16.f16.f32 "
                         "{%0,%1,%2,%3}, {%4,%5,%6,%7}, {%8,%9}, {%0,%1,%2,%3};"
                         : "+f"(acc[nt][0]), "+f"(acc[nt][1]),
                           "+f"(acc[nt][2]), "+f"(acc[nt][3])
                         : "r"(a0), "r"(a1), "r"(a2), "r"(a3), "r"(b.x), "r"(b.y));
        }
    }
}

#define ZACC(acc) do { _Pragma("unroll") for (int _n = 0; _n < 8; _n++) \
    { acc[_n][0]=0.f; acc[_n][1]=0.f; acc[_n][2]=0.f; acc[_n][3]=0.f; } } while (0)

#define STAGE_B(Bs, ch) do { __syncthreads();                                    \
    for (int _it = 0; _it < 8; _it++) {                                          \
        int _i = _it * 256 + tid;                                                \
        *(uint4*)&(Bs)[_i * 4] = *(const uint4*)&d_Bh[(ch) * 8192 + _i * 4];     \
    } __syncthreads(); } while (0)

// ---------------- prep kernels ----------------
__global__ void gate_kernel(const float* __restrict__ pos_enc, const float* __restrict__ Wg,
                            const float* __restrict__ bg) {
    int p = blockIdx.x, j = threadIdx.x;
    __shared__ float pe[PD];
    if (j < PD) pe[j] = pos_enc[p * PD + j];
    __syncthreads();
    float acc = bg[j];
#pragma unroll
    for (int k = 0; k < PD; k++) acc = fmaf(pe[k], Wg[k * HD + j], acc);
    d_gate[p * HD + j] = 2.0f / (1.0f + expf(-acc));
}

__global__ void init_h(const int* __restrict__ xidx, const float* __restrict__ sel,
                       const float* __restrict__ emb) {
    int v = blockIdx.x, j = threadIdx.x;
    float val = (j < VEMB) ? emb[xidx[v] * VEMB + j] : sel[v * 32 + (j - VEMB)];
    d_h0[v * HD + j] = val;
    d_hA[v * HD + j] = val;
}

__global__ void zero_misc() {
    int i = blockIdx.x * blockDim.x + threadIdx.x;
    if (i < NT * NN) d_cntT[i] = 0.0f;
    if (i < NN) { d_degi[i] = 0; d_fill[i] = 0; }
}
__global__ void cnt_kernel(const int* __restrict__ dst, const int* __restrict__ etype) {
    int e = blockIdx.x * blockDim.x + threadIdx.x;
    if (e < EE) {
        atomicAdd(&d_cntT[etype[e] * NN + dst[e]], 1.0f);
        atomicAdd(&d_degi[dst[e]], 1);
    }
}
__global__ void invden_kernel() {
    int v = blockIdx.x * blockDim.x + threadIdx.x;
    if (v < NN) d_invden[v] = 1.0f / fmaxf((float)d_degi[v], 1.0f);
}

__global__ void scanA() {
    __shared__ int s[1024];
    int b = blockIdx.x, t = threadIdx.x;
    int i = b * 1024 + t;
    s[t] = (i < NN) ? d_degi[i] : 0;
    __syncthreads();
#pragma unroll
    for (int off = 1; off < 1024; off <<= 1) {
        int x = (t >= off) ? s[t - off] : 0;
        __syncthreads();
        s[t] += x;
        __syncthreads();
    }
    if (i < NN) d_rowtmp[i] = s[t];
    if (t == 1023) d_bsum[b] = s[1023];
}
__global__ void scanB() {
    if (threadIdx.x == 0) {
        int run = 0;
        for (int b = 0; b < 98; b++) { int x = d_bsum[b]; d_bsum[b] = run; run += x; }
    }
}
__global__ void scanC() {
    int i = blockIdx.x * blockDim.x + threadIdx.x;
    if (i < NN) d_rowp[i] = d_rowtmp[i] - d_degi[i] + d_bsum[i >> 10];
}
__global__ void fill_kernel(const int* __restrict__ src, const int* __restrict__ dst,
                            const int* __restrict__ etype, const int* __restrict__ epos) {
    int e = blockIdx.x * blockDim.x + threadIdx.x;
    if (e < EE) {
        int dv = dst[e];
        int slot = d_rowp[dv] + atomicAdd(&d_fill[dv], 1);
        d_epk[slot] = (unsigned)src[e] | ((unsigned)epos[e] << 17) | ((unsigned)etype[e] << 27);
    }
}

// chunks: 0..2 Wt[t] (B[k][n]=Wt[t][k][n]); 3..5 Wih r/z/n (B[k][o]=Wih[o][k]);
//         6..8 Whh r/z/n; 9..10 W1 halves (B[k][j]=W1[k or 128+k][j])
__global__ void bprep(const float* __restrict__ Wt, const float* __restrict__ Wih,
                      const float* __restrict__ Whh, const float* __restrict__ W1) {
    int c = blockIdx.x;
    for (int i = threadIdx.x; i < 8192; i += blockDim.x) {
        int j = i & 1, tig = (i >> 1) & 3, n = (i >> 3) & 127, ks = i >> 10;
        int k0 = ks * 16 + j * 8 + tig * 2;
        float lo, hi;
        if (c < 3)       { lo = Wt[c * 16384 + k0 * HD + n];       hi = Wt[c * 16384 + (k0 + 1) * HD + n]; }
        else if (c < 6)  { lo = Wih[((c - 3) * 128 + n) * HD + k0]; hi = Wih[((c - 3) * 128 + n) * HD + k0 + 1]; }
        else if (c < 9)  { lo = Whh[((c - 6) * 128 + n) * HD + k0]; hi = Whh[((c - 6) * 128 + n) * HD + k0 + 1]; }
        else if (c == 9) { lo = W1[k0 * HD + n];                    hi = W1[(k0 + 1) * HD + n]; }
        else             { lo = W1[(128 + k0) * HD + n];            hi = W1[(129 + k0) * HD + n]; }
        d_Bh[c * 8192 + i] = packh2(lo, hi);
    }
}

// ---------------- fused iteration kernel ----------------
// byte offsets: AH0 0 | AH1 17408 | AH2 34816 | HH 52224 | BS 69632 (32768) |
//   SBT 102400 | SBIH 103936 | SBHH 105472 | SCNT 107008 (192f) | SINV 107776 (64f)
#define OB_AH0 0
#define OB_AH1 17408
#define OB_AH2 34816
#define OB_HH  52224
#define OB_BS  69632
#define OB_BT  102400
#define OB_BIH 103936
#define OB_BHH 105472
#define OB_CNT 107008
#define OB_INV 107776
#define SMEM_IT 108032

__global__ __launch_bounds__(256, 2) void iter_kernel(int dir,
                                                      const float* __restrict__ bih,
                                                      const float* __restrict__ bhh,
                                                      const float* __restrict__ bt) {
    extern __shared__ unsigned char smraw[];
    const float* hin  = dir ? d_hB : d_hA;
    float*       hout = dir ? d_hA : d_hB;
    unsigned* AH0 = (unsigned*)(smraw + OB_AH0);
    unsigned* AH1 = (unsigned*)(smraw + OB_AH1);
    unsigned* AH2 = (unsigned*)(smraw + OB_AH2);
    unsigned* HH  = (unsigned*)(smraw + OB_HH);
    unsigned* Bs  = (unsigned*)(smraw + OB_BS);
    float* sbt  = (float*)(smraw + OB_BT);
    float* sbih = (float*)(smraw + OB_BIH);
    float* sbhh = (float*)(smraw + OB_BHH);
    float* scnt = (float*)(smraw + OB_CNT);   // cnt_t * invden
    float* sinv = (float*)(smraw + OB_INV);

    int tid = threadIdx.x, lane = tid & 31, wid = tid >> 5;
    int g = lane >> 2, tig = lane & 3;
    int r0 = (wid & 3) * 16, c0 = (wid >> 2) * 64;
    int tile0 = blockIdx.x * 64;

    for (int i = tid; i < 384; i += 256) { sbt[i] = bt[i]; sbih[i] = bih[i]; sbhh[i] = bhh[i]; }
    if (tid < 64) {
        int v = tile0 + tid;
        bool ok = v < NN;
        float inv = ok ? d_invden[v] : 0.f;
        sinv[tid]       = inv;
        scnt[tid]       = ok ? d_cntT[v] * inv : 0.f;
        scnt[64 + tid]  = ok ? d_cntT[NN + v] * inv : 0.f;
        scnt[128 + tid] = ok ? d_cntT[2 * NN + v] * inv : 0.f;
    }
    // stage h_prev as fp16 MMA tile
    for (int it = 0; it < 8; it++) {
        int i = it * 256 + tid, r = i >> 5, q = i & 31, v = tile0 + r;
        float4 val = (v < NN) ? *(const float4*)&hin[v * HD + q * 4]
                              : make_float4(0.f, 0.f, 0.f, 0.f);
        uint2 o;
        o.x = packh2(val.x, val.y);
        o.y = packh2(val.z, val.w);
        *(uint2*)&HH[r * APW + q * 2] = o;
    }
    __syncthreads();

    // ---- CSR gather: A_t[r][:] = invden * sum_{e->r, type t} h_in[src] * gate[pos] ----
    for (int r = wid; r < 64; r += 8) {
        int v = tile0 + r;
        float4 a0 = make_float4(0.f, 0.f, 0.f, 0.f), a1 = a0, a2 = a0;
        if (v < NN) {
            int st = d_rowp[v], dg = d_degi[v];
            for (int e = 0; e < dg; e += 4) {
                int m = dg - e;
                unsigned wd[4];
                float4 hv[4], gv[4];
#pragma unroll
                for (int i = 0; i < 4; i++)
                    wd[i] = (i < m) ? d_epk[st + e + i] : 0xFFFFFFFFu;
#pragma unroll
                for (int i = 0; i < 4; i++) {
                    if (wd[i] != 0xFFFFFFFFu) {
                        int s = wd[i] & 0x1FFFF, p = (wd[i] >> 17) & 0x3FF;
                        hv[i] = *(const float4*)&hin[s * HD + lane * 4];
                        gv[i] = *(const float4*)&d_gate[p * HD + lane * 4];
                    }
                }
#pragma unroll
                for (int i = 0; i < 4; i++) {
                    if (wd[i] != 0xFFFFFFFFu) {
                        int t = wd[i] >> 27;
                        float4 mv;
                        mv.x = hv[i].x * gv[i].x; mv.y = hv[i].y * gv[i].y;
                        mv.z = hv[i].z * gv[i].z; mv.w = hv[i].w * gv[i].w;
                        if (t == 0) { a0.x += mv.x; a0.y += mv.y; a0.z += mv.z; a0.w += mv.w; }
                        else if (t == 1) { a1.x += mv.x; a1.y += mv.y; a1.z += mv.z; a1.w += mv.w; }
                        else { a2.x += mv.x; a2.y += mv.y; a2.z += mv.z; a2.w += mv.w; }
                    }
                }
            }
            float iv = sinv[r];
            a0.x *= iv; a0.y *= iv; a0.z *= iv; a0.w *= iv;
            a1.x *= iv; a1.y *= iv; a1.z *= iv; a1.w *= iv;
            a2.x *= iv; a2.y *= iv; a2.z *= iv; a2.w *= iv;
        }
        uint2 o;
        o.x = packh2(a0.x, a0.y); o.y = packh2(a0.z, a0.w);
        *(uint2*)&AH0[r * APW + lane * 2] = o;
        o.x = packh2(a1.x, a1.y); o.y = packh2(a1.z, a1.w);
        *(uint2*)&AH1[r * APW + lane * 2] = o;
        o.x = packh2(a2.x, a2.y); o.y = packh2(a2.z, a2.w);
        *(uint2*)&AH2[r * APW + lane * 2] = o;
    }

    // ---- stage 1: acc = sum_t A_t @ Wt[t]  (A pre-scaled by invden) ----
    float acc[8][4];
    ZACC(acc);
    STAGE_B(Bs, 0); gemm_h(AH0, Bs, r0, c0, g, tig, acc);
    STAGE_B(Bs, 1); gemm_h(AH1, Bs, r0, c0, g, tig, acc);
    STAGE_B(Bs, 2); gemm_h(AH2, Bs, r0, c0, g, tig, acc);
    __syncthreads();
    // epilogue: agg = acc + sum_t (cnt_t*inv)*bt_t  -> AH0 (fp16)
#pragma unroll
    for (int nt = 0; nt < 8; nt++)
#pragma unroll
        for (int i2 = 0; i2 < 2; i2++) {
            int row = r0 + g + i2 * 8;
            int colb = c0 + nt * 8 + 2 * tig;
            float v0 = acc[nt][i2 * 2 + 0] + scnt[row] * sbt[colb] +
                       scnt[64 + row] * sbt[128 + colb] + scnt[128 + row] * sbt[256 + colb];
            float v1 = acc[nt][i2 * 2 + 1] + scnt[row] * sbt[colb + 1] +
                       scnt[64 + row] * sbt[128 + colb + 1] + scnt[128 + row] * sbt[256 + colb + 1];
            AH0[row * APW + (colb >> 1)] = packh2(v0, v1);
        }
    __syncthreads();

    // ---- stage 2: GRU ----
    float rr[8][4];

    // r = sigma(agg@Wih_r + h@Whh_r + b)
    ZACC(acc);
    STAGE_B(Bs, 3); gemm_h(AH0, Bs, r0, c0, g, tig, acc);
    STAGE_B(Bs, 6); gemm_h(HH,  Bs, r0, c0, g, tig, acc);
#pragma unroll
    for (int nt = 0; nt < 8; nt++)
#pragma unroll
        for (int i = 0; i < 4; i++) {
            int col = c0 + nt * 8 + 2 * tig + (i & 1);
            rr[nt][i] = sigf(acc[nt][i] + sbih[col] + sbhh[col]);
        }

    // rghn = r * (h@Whh_n + bhh_n)
    ZACC(acc);
    STAGE_B(Bs, 8); gemm_h(HH, Bs, r0, c0, g, tig, acc);
#pragma unroll
    for (int nt = 0; nt < 8; nt++)
#pragma unroll
        for (int i = 0; i < 4; i++) {
            int col = c0 + nt * 8 + 2 * tig + (i & 1);
            rr[nt][i] = rr[nt][i] * (acc[nt][i] + sbhh[256 + col]);
        }

    // n = tanh(agg@Wih_n + bih_n + rghn)
    ZACC(acc);
    STAGE_B(Bs, 5); gemm_h(AH0, Bs, r0, c0, g, tig, acc);
#pragma unroll
    for (int nt = 0; nt < 8; nt++)
#pragma unroll
        for (int i = 0; i < 4; i++) {
            int col = c0 + nt * 8 + 2 * tig + (i & 1);
            rr[nt][i] = tanhf(acc[nt][i] + sbih[256 + col] + rr[nt][i]);
        }

    // z = sigma(agg@Wih_z + h@Whh_z + b);  h_new = (1-z)*n + z*h_prev
    ZACC(acc);
    STAGE_B(Bs, 4); gemm_h(AH0, Bs, r0, c0, g, tig, acc);
    STAGE_B(Bs, 7); gemm_h(HH,  Bs, r0, c0, g, tig, acc);
#pragma unroll
    for (int nt = 0; nt < 8; nt++)
#pragma unroll
        for (int i2 = 0; i2 < 2; i2++) {
            int row = r0 + g + i2 * 8;
            int v = tile0 + row;
            if (v < NN) {
                int colb = c0 + nt * 8 + 2 * tig;
                float z0 = sigf(acc[nt][i2 * 2 + 0] + sbih[128 + colb] + sbhh[128 + colb]);
                float z1 = sigf(acc[nt][i2 * 2 + 1] + sbih[129 + colb] + sbhh[129 + colb]);
                float2 hp = *(const float2*)&hin[v * HD + colb];   // exact fp32 h_prev
                float2 o;
                o.x = (1.f - z0) * rr[nt][i2 * 2 + 0] + z0 * hp.x;
                o.y = (1.f - z1) * rr[nt][i2 * 2 + 1] + z1 * hp.y;
                *(float2*)&hout[v * HD + colb] = o;
            }
        }
}

// ---------------- readout ----------------
// byte offsets: HA 0 | H0 17408 | BS 34816 (32768) | sb1 67584 | sW2 68096 | sred 68608 (128f)
#define RB_H0  17408
#define RB_BS  34816
#define RB_B1  67584
#define RB_W2  68096
#define RB_RED 68608
#define SMEM_RO 69120

__global__ __launch_bounds__(256, 2) void readout_tc(const float* __restrict__ b1,
                                                     const float* __restrict__ W2,
                                                     const float* __restrict__ b2,
                                                     float* __restrict__ out) {
    extern __shared__ unsigned char smraw[];
    unsigned* HA  = (unsigned*)(smraw);
    unsigned* H0  = (unsigned*)(smraw + RB_H0);
    unsigned* Bs  = (unsigned*)(smraw + RB_BS);
    float* sb1  = (float*)(smraw + RB_B1);
    float* sW2  = (float*)(smraw + RB_W2);
    float* sred = (float*)(smraw + RB_RED);

    int tid = threadIdx.x, lane = tid & 31, wid = tid >> 5;
    int g = lane >> 2, tig = lane & 3;
    int r0 = (wid & 3) * 16, c0 = (wid >> 2) * 64;
    int tile0 = blockIdx.x * 64;

    if (tid < 128) { sb1[tid] = b1[tid]; sW2[tid] = W2[tid]; sred[tid] = 0.f; }
    for (int it = 0; it < 8; it++) {
        int i = it * 256 + tid, r = i >> 5, q = i & 31, v = tile0 + r;
        float4 h  = (v < NN) ? *(const float4*)&d_hA[v * HD + q * 4] : make_float4(0.f, 0.f, 0.f, 0.f);
        float4 h0 = (v < NN) ? *(const float4*)&d_h0[v * HD + q * 4] : make_float4(0.f, 0.f, 0.f, 0.f);
        uint2 o;
        o.x = packh2(h.x, h.y);  o.y = packh2(h.z, h.w);
        *(uint2*)&HA[r * APW + q * 2] = o;
        o.x = packh2(h0.x, h0.y); o.y = packh2(h0.z, h0.w);
        *(uint2*)&H0[r * APW + q * 2] = o;
    }

    float acc[8][4];
    ZACC(acc);
    STAGE_B(Bs, 9);  gemm_h(HA, Bs, r0, c0, g, tig, acc);
    STAGE_B(Bs, 10); gemm_h(H0, Bs, r0, c0, g, tig, acc);

    float p0 = 0.f, p1 = 0.f;
#pragma unroll
    for (int nt = 0; nt < 8; nt++) {
        int colb = c0 + nt * 8 + 2 * tig;
        p0 += fmaxf(acc[nt][0] + sb1[colb],     0.f) * sW2[colb];
        p0 += fmaxf(acc[nt][1] + sb1[colb + 1], 0.f) * sW2[colb + 1];
        p1 += fmaxf(acc[nt][2] + sb1[colb],     0.f) * sW2[colb];
        p1 += fmaxf(acc[nt][3] + sb1[colb + 1], 0.f) * sW2[colb + 1];
    }
    p0 += __shfl_down_sync(0xffffffffu, p0, 1, 4);
    p0 += __shfl_down_sync(0xffffffffu, p0, 2, 4);
    p1 += __shfl_down_sync(0xffffffffu, p1, 1, 4);
    p1 += __shfl_down_sync(0xffffffffu, p1, 2, 4);
    if (tig == 0) {
        int wn = wid >> 2;
        sred[wn * 64 + r0 + g]     = p0;
        sred[wn * 64 + r0 + g + 8] = p1;
    }
    __syncthreads();
    if (tid < 64) {
        int v = tile0 + tid;
        if (v < NN) out[v] = sred[tid] + sred[64 + tid] + b2[0];
    }
}

// ---------------- launch ----------------
extern "C" void kernel_launch(void* const* d_in, const int* in_sizes, int n_in,
                              void* d_out, int out_size) {
    const int*   xidx    = (const int*)d_in[0];
    const float* sel     = (const float*)d_in[1];
    const int*   eidx    = (const int*)d_in[2];
    const int*   etype   = (const int*)d_in[3];
    const int*   epos    = (const int*)d_in[4];
    const float* emb     = (const float*)d_in[5];
    const float* pos_enc = (const float*)d_in[6];
    const float* Wg      = (const float*)d_in[7];
    const float* bg      = (const float*)d_in[8];
    const float* Wt      = (const float*)d_in[9];
    const float* bt      = (const float*)d_in[10];
    const float* Wih     = (const float*)d_in[11];
    const float* Whh     = (const float*)d_in[12];
    const float* bih     = (const float*)d_in[13];
    const float* bhh     = (const float*)d_in[14];
    const float* W1      = (const float*)d_in[15];
    const float* b1      = (const float*)d_in[16];
    const float* W2      = (const float*)d_in[17];
    const float* b2      = (const float*)d_in[18];
    const int* src = eidx;
    const int* dst = eidx + EE;
    float* out = (float*)d_out;

    cudaFuncSetAttribute(iter_kernel, cudaFuncAttributeMaxDynamicSharedMemorySize, SMEM_IT);
    cudaFuncSetAttribute(readout_tc, cudaFuncAttributeMaxDynamicSharedMemorySize, SMEM_RO);

    gate_kernel<<<NPOS, HD>>>(pos_enc, Wg, bg);
    init_h<<<NN, HD>>>(xidx, sel, emb);
    zero_misc<<<(NT * NN + 255) / 256, 256>>>();
    cnt_kernel<<<(EE + 255) / 256, 256>>>(dst, etype);
    invden_kernel<<<(NN + 255) / 256, 256>>>();
    scanA<<<98, 1024>>>();
    scanB<<<1, 32>>>();
    scanC<<<(NN + 255) / 256, 256>>>();
    fill_kernel<<<(EE + 255) / 256, 256>>>(src, dst, etype, epos);
    bprep<<<11, 256>>>(Wt, Wih, Whh, W1);

    for (int it = 0; it < 6; it++)
        iter_kernel<<<NT64, 256, SMEM_IT>>>(it & 1, bih, bhh, bt);

    readout_tc<<<NT64, 256, SMEM_RO>>>(b1, W2, b2, out);
}